// round 9
// baseline (speedup 1.0000x reference)
#include <cuda_runtime.h>
#include <cuda_bf16.h>

#define IMG_H 512
#define IMG_W 512
#define IMG_HW (IMG_H * IMG_W)
#define OUT_H 510
#define OUT_W 510
#define WIN_PER_WARP 30
#define SEGS 17                              // 17 * 30 = 510 windows per row
#define NWU (SEGS * OUT_H)                   // 8670 warp-units
#define BLOCK 128
#define NWARP (BLOCK / 32)
#define NBLK ((NWU + NWARP - 1) / NWARP)     // 2168

// Scratch for deterministic fused reduction (no device allocation allowed).
__device__ double g_partials[NBLK];
__device__ unsigned int g_ticket = 0;

__device__ __forceinline__ float win3(float x) {
    // window stat = colstat(l) + colstat(l+1) + colstat(l+2)
    const float x1 = __shfl_down_sync(0xFFFFFFFFu, x, 1);
    const float x2 = __shfl_down_sync(0xFFFFFFFFu, x, 2);
    return x + x1 + x2;
}

__global__ void __launch_bounds__(BLOCK) ml_col_kernel(
    const float* __restrict__ tgt, const float* __restrict__ sty,
    float* __restrict__ out)
{
    const int tid = threadIdx.x;
    const int lane = tid & 31;
    const int wid = tid >> 5;
    const int wu = blockIdx.x * NWARP + wid;

    float contrib = 0.0f;
    if (wu < NWU) {
        const int row = wu / SEGS;
        const int seg = wu - row * SEGS;
        const int col = seg * WIN_PER_WARP + lane;     // 0..511, always in-bounds
        const int base = row * IMG_W + col;

        // ---- 18 coalesced loads: 3 rows x 3 channels x {target, style} ----
        float a0r0 = __ldg(tgt + 0 * IMG_HW + base);
        float a0r1 = __ldg(tgt + 0 * IMG_HW + base + IMG_W);
        float a0r2 = __ldg(tgt + 0 * IMG_HW + base + 2 * IMG_W);
        float a1r0 = __ldg(tgt + 1 * IMG_HW + base);
        float a1r1 = __ldg(tgt + 1 * IMG_HW + base + IMG_W);
        float a1r2 = __ldg(tgt + 1 * IMG_HW + base + 2 * IMG_W);
        float a2r0 = __ldg(tgt + 2 * IMG_HW + base);
        float a2r1 = __ldg(tgt + 2 * IMG_HW + base + IMG_W);
        float a2r2 = __ldg(tgt + 2 * IMG_HW + base + 2 * IMG_W);
        float v0r0 = __ldg(sty + 0 * IMG_HW + base);
        float v0r1 = __ldg(sty + 0 * IMG_HW + base + IMG_W);
        float v0r2 = __ldg(sty + 0 * IMG_HW + base + 2 * IMG_W);
        float v1r0 = __ldg(sty + 1 * IMG_HW + base);
        float v1r1 = __ldg(sty + 1 * IMG_HW + base + IMG_W);
        float v1r2 = __ldg(sty + 1 * IMG_HW + base + 2 * IMG_W);
        float v2r0 = __ldg(sty + 2 * IMG_HW + base);
        float v2r1 = __ldg(sty + 2 * IMG_HW + base + IMG_W);
        float v2r2 = __ldg(sty + 2 * IMG_HW + base + 2 * IMG_W);

        // ---- Per-column statistics (22 values; |v|^2 channel-combined) ----
        const float cs0 = a0r0 + a0r1 + a0r2;
        const float cs1 = a1r0 + a1r1 + a1r2;
        const float cs2 = a2r0 + a2r1 + a2r2;
        const float cg00 = a0r0 * a0r0 + a0r1 * a0r1 + a0r2 * a0r2;
        const float cg01 = a0r0 * a1r0 + a0r1 * a1r1 + a0r2 * a1r2;
        const float cg02 = a0r0 * a2r0 + a0r1 * a2r1 + a0r2 * a2r2;
        const float cg11 = a1r0 * a1r0 + a1r1 * a1r1 + a1r2 * a1r2;
        const float cg12 = a1r0 * a2r0 + a1r1 * a2r1 + a1r2 * a2r2;
        const float cg22 = a2r0 * a2r0 + a2r1 * a2r1 + a2r2 * a2r2;
        const float csv0 = v0r0 + v0r1 + v0r2;
        const float csv1 = v1r0 + v1r1 + v1r2;
        const float csv2 = v2r0 + v2r1 + v2r2;
        const float cQ  = v0r0 * v0r0 + v0r1 * v0r1 + v0r2 * v0r2
                        + v1r0 * v1r0 + v1r1 * v1r1 + v1r2 * v1r2
                        + v2r0 * v2r0 + v2r1 * v2r1 + v2r2 * v2r2;
        const float cY00 = a0r0 * v0r0 + a0r1 * v0r1 + a0r2 * v0r2;
        const float cY01 = a0r0 * v1r0 + a0r1 * v1r1 + a0r2 * v1r2;
        const float cY02 = a0r0 * v2r0 + a0r1 * v2r1 + a0r2 * v2r2;
        const float cY10 = a1r0 * v0r0 + a1r1 * v0r1 + a1r2 * v0r2;
        const float cY11 = a1r0 * v1r0 + a1r1 * v1r1 + a1r2 * v1r2;
        const float cY12 = a1r0 * v2r0 + a1r1 * v2r1 + a1r2 * v2r2;
        const float cY20 = a2r0 * v0r0 + a2r1 * v0r1 + a2r2 * v0r2;
        const float cY21 = a2r0 * v1r0 + a2r1 * v1r1 + a2r2 * v1r2;
        const float cY22 = a2r0 * v2r0 + a2r1 * v2r1 + a2r2 * v2r2;

        // ---- Window statistics via warp shuffles (lanes 0..29 valid) ----
        const float s0 = win3(cs0), s1 = win3(cs1), s2 = win3(cs2);
        float g00 = win3(cg00), g01 = win3(cg01), g02 = win3(cg02);
        float g11 = win3(cg11), g12 = win3(cg12), g22 = win3(cg22);
        const float sv0 = win3(csv0), sv1 = win3(csv1), sv2 = win3(csv2);
        const float Q   = win3(cQ);
        const float Y00 = win3(cY00), Y01 = win3(cY01), Y02 = win3(cY02);
        const float Y10 = win3(cY10), Y11 = win3(cY11), Y12 = win3(cY12);
        const float Y20 = win3(cY20), Y21 = win3(cY21), Y22 = win3(cY22);

        if (lane < WIN_PER_WARP) {
            const float inv9 = 1.0f / 9.0f;
            const float eps9 = 1e-7f / 9.0f;
            const float mu0 = s0 * inv9, mu1 = s1 * inv9, mu2 = s2 * inv9;

            g00 = g00 * inv9 - mu0 * mu0 + eps9;
            g01 = g01 * inv9 - mu0 * mu1;
            g02 = g02 * inv9 - mu0 * mu2;
            g11 = g11 * inv9 - mu1 * mu1 + eps9;
            g12 = g12 * inv9 - mu1 * mu2;
            g22 = g22 * inv9 - mu2 * mu2 + eps9;

            const float adj00 = g11 * g22 - g12 * g12;
            const float adj01 = g02 * g12 - g01 * g22;
            const float adj02 = g01 * g12 - g02 * g11;
            const float adj11 = g00 * g22 - g02 * g02;
            const float adj12 = g01 * g02 - g00 * g12;
            const float adj22 = g00 * g11 - g01 * g01;
            const float det = g00 * adj00 + g01 * adj01 + g02 * adj02;
            const float invdet = 1.0f / det;

            // Q-term folded in once: contrib = Q - sum_ch (s^2 + y^T adj y / det)/9
            float acc9 = 0.0f;   // accumulates (s^2 + quad*invdet) over channels
            // ch 0
            {
                const float s = sv0;
                const float y0 = Y00 - mu0 * s, y1 = Y10 - mu1 * s, y2 = Y20 - mu2 * s;
                const float quad = adj00 * y0 * y0 + adj11 * y1 * y1 + adj22 * y2 * y2
                                 + 2.0f * (adj01 * y0 * y1 + adj02 * y0 * y2 + adj12 * y1 * y2);
                acc9 += s * s + quad * invdet;
            }
            // ch 1
            {
                const float s = sv1;
                const float y0 = Y01 - mu0 * s, y1 = Y11 - mu1 * s, y2 = Y21 - mu2 * s;
                const float quad = adj00 * y0 * y0 + adj11 * y1 * y1 + adj22 * y2 * y2
                                 + 2.0f * (adj01 * y0 * y1 + adj02 * y0 * y2 + adj12 * y1 * y2);
                acc9 += s * s + quad * invdet;
            }
            // ch 2
            {
                const float s = sv2;
                const float y0 = Y02 - mu0 * s, y1 = Y12 - mu1 * s, y2 = Y22 - mu2 * s;
                const float quad = adj00 * y0 * y0 + adj11 * y1 * y1 + adj22 * y2 * y2
                                 + 2.0f * (adj01 * y0 * y1 + adj02 * y0 * y2 + adj12 * y1 * y2);
                acc9 += s * s + quad * invdet;
            }
            contrib = Q - acc9 * inv9;
        }
    }

    // ---- Block reduction: warp shuffles (deterministic fixed tree) ----
    double acc = (double)contrib;
    #pragma unroll
    for (int off = 16; off > 0; off >>= 1)
        acc += __shfl_down_sync(0xFFFFFFFFu, acc, off);

    __shared__ double warp_sums[NWARP];
    if (lane == 0) warp_sums[wid] = acc;
    __syncthreads();

    __shared__ bool is_last;
    if (tid == 0) {
        double bsum = 0.0;
        #pragma unroll
        for (int i = 0; i < NWARP; i++) bsum += warp_sums[i];
        g_partials[blockIdx.x] = bsum;
        unsigned int t;
        asm volatile("atom.release.gpu.global.add.u32 %0, [%1], %2;"
                     : "=r"(t) : "l"(&g_ticket), "r"(1u) : "memory");
        is_last = (t == (unsigned)(NBLK - 1));
    }
    __syncthreads();

    // ---- Last block performs the final deterministic reduction ----
    if (is_last) {
        double a = 0.0;
        for (int i = tid; i < NBLK; i += BLOCK) {
            double v;
            asm volatile("ld.acquire.gpu.global.f64 %0, [%1];"
                         : "=d"(v) : "l"(&g_partials[i]) : "memory");
            a += v;
        }
        #pragma unroll
        for (int off = 16; off > 0; off >>= 1)
            a += __shfl_down_sync(0xFFFFFFFFu, a, off);
        if (lane == 0) warp_sums[wid] = a;
        __syncthreads();
        if (tid == 0) {
            double tot = 0.0;
            #pragma unroll
            for (int i = 0; i < NWARP; i++) tot += warp_sums[i];
            out[0] = (float)tot;
            g_ticket = 0;   // reset for next graph replay
        }
    }
}

extern "C" void kernel_launch(void* const* d_in, const int* in_sizes, int n_in,
                              void* d_out, int out_size)
{
    const float* tgt = (const float*)d_in[0];   // target  (3, 512, 512) fp32
    const float* sty = (const float*)d_in[1];   // style   (3, 512, 512) fp32
    float* out = (float*)d_out;

    ml_col_kernel<<<NBLK, BLOCK>>>(tgt, sty, out);
}

// round 10
// speedup vs baseline: 1.4837x; 1.4837x over previous
#include <cuda_runtime.h>
#include <cuda_bf16.h>

#define IMG_H 512
#define IMG_W 512
#define IMG_HW (IMG_H * IMG_W)
#define OUT_H 510
#define OUT_W 510
#define WIN_PER_WARP 30
#define SEGS 17                              // 17 * 30 = 510 windows per row
#define NWU (SEGS * OUT_H)                   // 8670 warp-units
#define BLOCK 256
#define NWARP (BLOCK / 32)
#define NBLK ((NWU + NWARP - 1) / NWARP)     // 1084

#define FIX_SCALE 16777216.0                 // 2^24
#define COUNT_SHIFT 52

// Single packed accumulator: bits [52:63] = arrival count, low bits = fixed-point sum.
// Integer adds are associative+commutative -> bit-deterministic total.
__device__ unsigned long long g_acc = 0ULL;

__device__ __forceinline__ float win3(float x) {
    // window stat = colstat(l) + colstat(l+1) + colstat(l+2)
    const float x1 = __shfl_down_sync(0xFFFFFFFFu, x, 1);
    const float x2 = __shfl_down_sync(0xFFFFFFFFu, x, 2);
    return x + x1 + x2;
}

__global__ void __launch_bounds__(BLOCK) ml_col_kernel(
    const float* __restrict__ tgt, const float* __restrict__ sty,
    float* __restrict__ out)
{
    const int tid = threadIdx.x;
    const int lane = tid & 31;
    const int wid = tid >> 5;
    const int wu = blockIdx.x * NWARP + wid;

    float contrib = 0.0f;
    if (wu < NWU) {
        const int row = wu / SEGS;
        const int seg = wu - row * SEGS;
        const int col = seg * WIN_PER_WARP + lane;     // 0..511, always in-bounds
        const int base = row * IMG_W + col;

        // ---- 18 coalesced loads: 3 rows x 3 channels x {target, style} ----
        float a0r0 = __ldg(tgt + 0 * IMG_HW + base);
        float a0r1 = __ldg(tgt + 0 * IMG_HW + base + IMG_W);
        float a0r2 = __ldg(tgt + 0 * IMG_HW + base + 2 * IMG_W);
        float a1r0 = __ldg(tgt + 1 * IMG_HW + base);
        float a1r1 = __ldg(tgt + 1 * IMG_HW + base + IMG_W);
        float a1r2 = __ldg(tgt + 1 * IMG_HW + base + 2 * IMG_W);
        float a2r0 = __ldg(tgt + 2 * IMG_HW + base);
        float a2r1 = __ldg(tgt + 2 * IMG_HW + base + IMG_W);
        float a2r2 = __ldg(tgt + 2 * IMG_HW + base + 2 * IMG_W);
        float v0r0 = __ldg(sty + 0 * IMG_HW + base);
        float v0r1 = __ldg(sty + 0 * IMG_HW + base + IMG_W);
        float v0r2 = __ldg(sty + 0 * IMG_HW + base + 2 * IMG_W);
        float v1r0 = __ldg(sty + 1 * IMG_HW + base);
        float v1r1 = __ldg(sty + 1 * IMG_HW + base + IMG_W);
        float v1r2 = __ldg(sty + 1 * IMG_HW + base + 2 * IMG_W);
        float v2r0 = __ldg(sty + 2 * IMG_HW + base);
        float v2r1 = __ldg(sty + 2 * IMG_HW + base + IMG_W);
        float v2r2 = __ldg(sty + 2 * IMG_HW + base + 2 * IMG_W);

        // ---- Per-column statistics (22 values; |v|^2 channel-combined) ----
        const float cs0 = a0r0 + a0r1 + a0r2;
        const float cs1 = a1r0 + a1r1 + a1r2;
        const float cs2 = a2r0 + a2r1 + a2r2;
        const float cg00 = a0r0 * a0r0 + a0r1 * a0r1 + a0r2 * a0r2;
        const float cg01 = a0r0 * a1r0 + a0r1 * a1r1 + a0r2 * a1r2;
        const float cg02 = a0r0 * a2r0 + a0r1 * a2r1 + a0r2 * a2r2;
        const float cg11 = a1r0 * a1r0 + a1r1 * a1r1 + a1r2 * a1r2;
        const float cg12 = a1r0 * a2r0 + a1r1 * a2r1 + a1r2 * a2r2;
        const float cg22 = a2r0 * a2r0 + a2r1 * a2r1 + a2r2 * a2r2;
        const float csv0 = v0r0 + v0r1 + v0r2;
        const float csv1 = v1r0 + v1r1 + v1r2;
        const float csv2 = v2r0 + v2r1 + v2r2;
        const float cQ  = v0r0 * v0r0 + v0r1 * v0r1 + v0r2 * v0r2
                        + v1r0 * v1r0 + v1r1 * v1r1 + v1r2 * v1r2
                        + v2r0 * v2r0 + v2r1 * v2r1 + v2r2 * v2r2;
        const float cY00 = a0r0 * v0r0 + a0r1 * v0r1 + a0r2 * v0r2;
        const float cY01 = a0r0 * v1r0 + a0r1 * v1r1 + a0r2 * v1r2;
        const float cY02 = a0r0 * v2r0 + a0r1 * v2r1 + a0r2 * v2r2;
        const float cY10 = a1r0 * v0r0 + a1r1 * v0r1 + a1r2 * v0r2;
        const float cY11 = a1r0 * v1r0 + a1r1 * v1r1 + a1r2 * v1r2;
        const float cY12 = a1r0 * v2r0 + a1r1 * v2r1 + a1r2 * v2r2;
        const float cY20 = a2r0 * v0r0 + a2r1 * v0r1 + a2r2 * v0r2;
        const float cY21 = a2r0 * v1r0 + a2r1 * v1r1 + a2r2 * v1r2;
        const float cY22 = a2r0 * v2r0 + a2r1 * v2r1 + a2r2 * v2r2;

        // ---- Window statistics via warp shuffles (lanes 0..29 valid) ----
        const float s0 = win3(cs0), s1 = win3(cs1), s2 = win3(cs2);
        float g00 = win3(cg00), g01 = win3(cg01), g02 = win3(cg02);
        float g11 = win3(cg11), g12 = win3(cg12), g22 = win3(cg22);
        const float sv0 = win3(csv0), sv1 = win3(csv1), sv2 = win3(csv2);
        const float Q   = win3(cQ);
        const float Y00 = win3(cY00), Y01 = win3(cY01), Y02 = win3(cY02);
        const float Y10 = win3(cY10), Y11 = win3(cY11), Y12 = win3(cY12);
        const float Y20 = win3(cY20), Y21 = win3(cY21), Y22 = win3(cY22);

        if (lane < WIN_PER_WARP) {
            const float inv9 = 1.0f / 9.0f;
            const float eps9 = 1e-7f / 9.0f;
            const float mu0 = s0 * inv9, mu1 = s1 * inv9, mu2 = s2 * inv9;

            g00 = g00 * inv9 - mu0 * mu0 + eps9;
            g01 = g01 * inv9 - mu0 * mu1;
            g02 = g02 * inv9 - mu0 * mu2;
            g11 = g11 * inv9 - mu1 * mu1 + eps9;
            g12 = g12 * inv9 - mu1 * mu2;
            g22 = g22 * inv9 - mu2 * mu2 + eps9;

            const float adj00 = g11 * g22 - g12 * g12;
            const float adj01 = g02 * g12 - g01 * g22;
            const float adj02 = g01 * g12 - g02 * g11;
            const float adj11 = g00 * g22 - g02 * g02;
            const float adj12 = g01 * g02 - g00 * g12;
            const float adj22 = g00 * g11 - g01 * g01;
            const float det = g00 * adj00 + g01 * adj01 + g02 * adj02;
            const float invdet = 1.0f / det;

            float acc9 = 0.0f;   // accumulates (s^2 + quad*invdet) over channels
            {
                const float s = sv0;
                const float y0 = Y00 - mu0 * s, y1 = Y10 - mu1 * s, y2 = Y20 - mu2 * s;
                const float quad = adj00 * y0 * y0 + adj11 * y1 * y1 + adj22 * y2 * y2
                                 + 2.0f * (adj01 * y0 * y1 + adj02 * y0 * y2 + adj12 * y1 * y2);
                acc9 += s * s + quad * invdet;
            }
            {
                const float s = sv1;
                const float y0 = Y01 - mu0 * s, y1 = Y11 - mu1 * s, y2 = Y21 - mu2 * s;
                const float quad = adj00 * y0 * y0 + adj11 * y1 * y1 + adj22 * y2 * y2
                                 + 2.0f * (adj01 * y0 * y1 + adj02 * y0 * y2 + adj12 * y1 * y2);
                acc9 += s * s + quad * invdet;
            }
            {
                const float s = sv2;
                const float y0 = Y02 - mu0 * s, y1 = Y12 - mu1 * s, y2 = Y22 - mu2 * s;
                const float quad = adj00 * y0 * y0 + adj11 * y1 * y1 + adj22 * y2 * y2
                                 + 2.0f * (adj01 * y0 * y1 + adj02 * y0 * y2 + adj12 * y1 * y2);
                acc9 += s * s + quad * invdet;
            }
            contrib = Q - acc9 * inv9;
        }
    }

    // ---- Block reduction: warp shuffles (deterministic fixed tree) ----
    double acc = (double)contrib;
    #pragma unroll
    for (int off = 16; off > 0; off >>= 1)
        acc += __shfl_down_sync(0xFFFFFFFFu, acc, off);

    __shared__ double warp_sums[NWARP];
    if (lane == 0) warp_sums[wid] = acc;
    __syncthreads();

    // ---- Fence-free packed-atomic finish (no release fence -> no L1 flush) ----
    if (tid == 0) {
        double bsum = 0.0;
        #pragma unroll
        for (int i = 0; i < NWARP; i++) bsum += warp_sums[i];

        // term = count-tick in bits [52:63] + fixed-point partial in low bits.
        const long long fx = __double2ll_rn(bsum * FIX_SCALE);
        const unsigned long long term = (1ULL << COUNT_SHIFT) + (unsigned long long)fx;
        const unsigned long long old = atomicAdd(&g_acc, term);

        if ((old >> COUNT_SHIFT) == (unsigned long long)(NBLK - 1)) {
            // This block's add completed the sum; total is known locally.
            const unsigned long long total = old + term;
            const long long value =
                (long long)(total - ((unsigned long long)NBLK << COUNT_SHIFT));
            out[0] = (float)((double)value * (1.0 / FIX_SCALE));
            // Reset for the next (graph-replayed) call; all adds for this call
            // are complete because same-address atomics are totally ordered.
            atomicExch(&g_acc, 0ULL);
        }
    }
}

extern "C" void kernel_launch(void* const* d_in, const int* in_sizes, int n_in,
                              void* d_out, int out_size)
{
    const float* tgt = (const float*)d_in[0];   // target  (3, 512, 512) fp32
    const float* sty = (const float*)d_in[1];   // style   (3, 512, 512) fp32
    float* out = (float*)d_out;

    ml_col_kernel<<<NBLK, BLOCK>>>(tgt, sty, out);
}